// round 8
// baseline (speedup 1.0000x reference)
#include <cuda_runtime.h>
#include <cuda_bf16.h>
#include <math.h>

#define N_NODES 65536
#define NN      131072          // both trees
#define MDIM    256
#define TM3     768
#define VOCABSZ 1000
#define MAXLEV  64

#define NGROUP  8
#define NSLOT   18
#define NBP     (NGROUP * NSLOT)    // 144 CTAs, 1/SM
#define PTHREADS 512
#define SMEM_DYN (16384 * 8)        // 131072 B: B1(12288 uint2) + B2(4096 uint2)

// ---------------- device scratch (static, allowed) ----------------
__device__ float g_hsum[(size_t)NN * MDIM];
__device__ float g_fcsum[(size_t)NN * MDIM];
__device__ float g_h[(size_t)NN * MDIM];
__device__ float g_c[(size_t)NN * MDIM];
__device__ float g_EA[(size_t)VOCABSZ * TM3];
__device__ float g_EB[(size_t)VOCABSZ * MDIM];
__device__ float g_HL[(size_t)VOCABSZ * MDIM];
__device__ float g_CL[(size_t)VOCABSZ * MDIM];
__device__ float g_FH[(size_t)VOCABSZ * MDIM];
__device__ float g_rootc[2 * MDIM];
__device__ float g_zero[MDIM];      // never written: stays zero

// fragment-packed tf32 weights: [kc][colblock][lane] -> (b0,b1)
__device__ uint2 g_Wp1[32 * 96 * 32];   // Wiouh, 768 cols = 96 colblocks
__device__ uint2 g_Wp2[32 * 32 * 32];   // Wfh,   256 cols = 32 colblocks

__device__ int g_parent[NN];
__device__ int g_tok[NN];
__device__ int g_anc[2][NN];
__device__ int g_dist[2][NN];
__device__ int g_childcnt[NN];
__device__ int g_lvlcnt_int[MAXLEV];
__device__ int g_lvlcnt_leaf[MAXLEV];
__device__ int g_lvloff[MAXLEV];
__device__ int g_curs_int[MAXLEV];
__device__ int g_curs_leaf[MAXLEV];
__device__ int g_order[NN];
__device__ int g_maxlev;

__device__ unsigned g_bcount = 0;
__device__ volatile unsigned g_bgen = 0;

__device__ __forceinline__ float sigm(float x) { return 1.f / (1.f + __expf(-x)); }

__device__ __forceinline__ unsigned tf32u(float x) {
    unsigned y;
    asm("cvt.rna.tf32.f32 %0, %1;" : "=r"(y) : "f"(x));
    return y;
}

__device__ __forceinline__ void mma8(float4& d, unsigned a0, unsigned a1, unsigned a2, unsigned a3,
                                     unsigned b0, unsigned b1) {
    asm volatile("mma.sync.aligned.m16n8k8.row.col.f32.tf32.tf32.f32 "
        "{%0,%1,%2,%3},{%4,%5,%6,%7},{%8,%9},{%0,%1,%2,%3};"
        : "+f"(d.x), "+f"(d.y), "+f"(d.z), "+f"(d.w)
        : "r"(a0), "r"(a1), "r"(a2), "r"(a3), "r"(b0), "r"(b1));
}

__device__ __forceinline__ void red2(float* p, float a, float b) {
    asm volatile("red.global.add.v2.f32 [%0], {%1, %2};"
                 :: "l"(p), "f"(a), "f"(b) : "memory");
}
__device__ __forceinline__ void red4(float* p, float a, float b, float c, float d) {
    asm volatile("red.global.add.v4.f32 [%0], {%1, %2, %3, %4};"
                 :: "l"(p), "f"(a), "f"(b), "f"(c), "f"(d) : "memory");
}

__device__ __forceinline__ void gsync() {
    __syncthreads();
    if (threadIdx.x == 0) {
        __threadfence();
        unsigned my = g_bgen;
        if (atomicInc(&g_bcount, gridDim.x - 1) == gridDim.x - 1) {
            g_bgen = my + 1;
        } else {
            while (g_bgen == my) { }
        }
        __threadfence();
    }
    __syncthreads();
}

// ---------------- setup ----------------
__global__ void clear_kernel() {
    size_t i = (size_t)blockIdx.x * blockDim.x + threadIdx.x;
    size_t tot4 = (size_t)NN * MDIM / 4;
    if (i < tot4) {
        float4 z = make_float4(0.f, 0.f, 0.f, 0.f);
        reinterpret_cast<float4*>(g_hsum)[i] = z;
        reinterpret_cast<float4*>(g_fcsum)[i] = z;
    }
    if (i < NN) g_childcnt[i] = 0;
    if (i < MAXLEV) {
        g_lvlcnt_int[i] = 0; g_lvlcnt_leaf[i] = 0;
        g_curs_int[i] = 0;   g_curs_leaf[i] = 0;
    }
}

__global__ void setup_kernel(const int* __restrict__ lt, const int* __restrict__ lp,
                             const int* __restrict__ rt, const int* __restrict__ rp) {
    int g = blockIdx.x * blockDim.x + threadIdx.x;
    if (g >= NN) return;
    int tok, par; bool root;
    if (g < N_NODES) {
        tok = lt[g]; root = (g == 0);
        par = root ? g : lp[g];
    } else {
        int i = g - N_NODES;
        tok = rt[i]; root = (i == 0);
        par = root ? g : (N_NODES + rp[i]);
    }
    g_tok[g] = tok; g_parent[g] = par;
    g_anc[0][g] = par;
    g_dist[0][g] = root ? 0 : 1;
    if (!root) atomicAdd(&g_childcnt[par], 1);
}

__global__ void doubling_kernel(int src) {
    int g = blockIdx.x * blockDim.x + threadIdx.x;
    if (g >= NN) return;
    int a = g_anc[src][g];
    g_dist[1 - src][g] = g_dist[src][g] + g_dist[src][a];
    g_anc[1 - src][g]  = g_anc[src][a];
}

__global__ void hist_kernel() {
    int g = blockIdx.x * blockDim.x + threadIdx.x;
    if (g >= NN) return;
    int d = g_dist[0][g]; if (d > MAXLEV - 1) d = MAXLEV - 1;
    if (g_childcnt[g] > 0) atomicAdd(&g_lvlcnt_int[d], 1);
    else                   atomicAdd(&g_lvlcnt_leaf[d], 1);
}

__global__ void scan_kernel() {
    if (threadIdx.x == 0) {
        int off = 0, maxl = 0;
        for (int l = 0; l < MAXLEV; l++) {
            g_lvloff[l] = off;
            int c = g_lvlcnt_int[l] + g_lvlcnt_leaf[l];
            if (c > 0) maxl = l;
            off += c;
        }
        g_maxlev = maxl;
    }
}

__global__ void scatter_kernel() {
    int g = blockIdx.x * blockDim.x + threadIdx.x;
    if (g >= NN) return;
    int d = g_dist[0][g]; if (d > MAXLEV - 1) d = MAXLEV - 1;
    int base = g_lvloff[d];
    if (g_childcnt[g] > 0) {
        int p = atomicAdd(&g_curs_int[d], 1);
        g_order[base + p] = g;
    } else {
        int p = atomicAdd(&g_curs_leaf[d], 1);
        g_order[base + g_lvlcnt_int[d] + p] = g;
    }
}

// weight pack kernels: lane holds (b0,b1) = W[k0+tig][col], W[k0+tig+4][col]
__global__ void pack1_kernel(const float* __restrict__ W) {   // Wiouh 256x768
    int idx = blockIdx.x * blockDim.x + threadIdx.x;
    if (idx >= 32 * 96 * 32) return;
    int lane = idx & 31;
    int cbi = (idx >> 5) % 96;
    int kc = idx / (96 * 32);
    int tig = lane & 3, gi = lane >> 2;
    int col = cbi * 8 + gi;
    float v0 = W[(size_t)(kc * 8 + tig) * TM3 + col];
    float v1 = W[(size_t)(kc * 8 + tig + 4) * TM3 + col];
    g_Wp1[idx] = make_uint2(tf32u(v0), tf32u(v1));
}
__global__ void pack2_kernel(const float* __restrict__ W) {   // Wfh 256x256
    int idx = blockIdx.x * blockDim.x + threadIdx.x;
    if (idx >= 32 * 32 * 32) return;
    int lane = idx & 31;
    int cbi = (idx >> 5) % 32;
    int kc = idx / (32 * 32);
    int tig = lane & 3, gi = lane >> 2;
    int col = cbi * 8 + gi;
    float v0 = W[(size_t)(kc * 8 + tig) * MDIM + col];
    float v1 = W[(size_t)(kc * 8 + tig + 4) * MDIM + col];
    g_Wp2[idx] = make_uint2(tf32u(v0), tf32u(v1));
}

// EA/EB: tiled over 8 vocab rows per block (weight reuse x8)
__global__ void eaeb_kernel(const float* __restrict__ emb,
                            const float* __restrict__ Wioux, const float* __restrict__ bioux,
                            const float* __restrict__ biouh,
                            const float* __restrict__ Wfx, const float* __restrict__ bfx,
                            const float* __restrict__ bfh) {
    int v0 = blockIdx.x * 8;
    int chunk = blockIdx.y;
    __shared__ float xs[8][MDIM];
    int t = threadIdx.x;
    #pragma unroll
    for (int i = 0; i < 8; i++) {
        int idx = t + i * 256;
        xs[idx >> 8][idx & 255] = emb[(size_t)v0 * MDIM + idx];
    }
    __syncthreads();
    float acc[8];
    #pragma unroll
    for (int r = 0; r < 8; r++) acc[r] = 0.f;
    if (chunk < 3) {
        int j = chunk * 256 + t;
        for (int k = 0; k < MDIM; k++) {
            float w = Wioux[(size_t)k * TM3 + j];
            #pragma unroll
            for (int r = 0; r < 8; r++) acc[r] += xs[r][k] * w;
        }
        float bias = bioux[j] + biouh[j];
        #pragma unroll
        for (int r = 0; r < 8; r++)
            g_EA[(size_t)(v0 + r) * TM3 + j] = acc[r] + bias;
    } else {
        int j = t;
        for (int k = 0; k < MDIM; k++) {
            float w = Wfx[(size_t)k * MDIM + j];
            #pragma unroll
            for (int r = 0; r < 8; r++) acc[r] += xs[r][k] * w;
        }
        float bias = bfx[j] + bfh[j];
        #pragma unroll
        for (int r = 0; r < 8; r++)
            g_EB[(size_t)(v0 + r) * MDIM + j] = acc[r] + bias;
    }
}

__global__ void leafhc_kernel() {
    int v = blockIdx.x, t = threadIdx.x;
    const float* ea = &g_EA[(size_t)v * TM3];
    float cc = sigm(ea[t]) * tanhf(ea[512 + t]);
    float hh = sigm(ea[256 + t]) * tanhf(cc);
    g_CL[(size_t)v * MDIM + t] = cc;
    g_HL[(size_t)v * MDIM + t] = hh;
}

// FH = HL @ Wfh, tiled over 8 vocab rows
__global__ void leaffh_kernel(const float* __restrict__ Wfh) {
    int v0 = blockIdx.x * 8;
    int t = threadIdx.x;
    __shared__ float hs[8][MDIM];
    #pragma unroll
    for (int i = 0; i < 8; i++) {
        int idx = t + i * 256;
        hs[idx >> 8][idx & 255] = g_HL[(size_t)v0 * MDIM + idx];
    }
    __syncthreads();
    float acc[8];
    #pragma unroll
    for (int r = 0; r < 8; r++) acc[r] = 0.f;
    for (int k = 0; k < MDIM; k++) {
        float w = Wfh[(size_t)k * MDIM + t];
        #pragma unroll
        for (int r = 0; r < 8; r++) acc[r] += hs[r][k] * w;
    }
    #pragma unroll
    for (int r = 0; r < 8; r++)
        g_FH[(size_t)(v0 + r) * MDIM + t] = acc[r];
}

__global__ void leafscatter_kernel() {
    int idx = blockIdx.x * blockDim.x + threadIdx.x;
    int g = idx >> 6;
    int c = (idx & 63) * 4;
    if (g >= NN) return;
    if (g_childcnt[g] > 0) return;
    int p = g_parent[g];
    int tok = g_tok[g], ptok = g_tok[p];
    float4 h4 = *(const float4*)&g_HL[(size_t)tok * MDIM + c];
    float4 c4 = *(const float4*)&g_CL[(size_t)tok * MDIM + c];
    float4 fh = *(const float4*)&g_FH[(size_t)tok * MDIM + c];
    float4 eb = *(const float4*)&g_EB[(size_t)ptok * MDIM + c];
    float f0 = sigm(fh.x + eb.x), f1 = sigm(fh.y + eb.y);
    float f2 = sigm(fh.z + eb.z), f3 = sigm(fh.w + eb.w);
    red4(&g_hsum[(size_t)p * MDIM + c], h4.x, h4.y, h4.z, h4.w);
    red4(&g_fcsum[(size_t)p * MDIM + c], f0 * c4.x, f1 * c4.y, f2 * c4.z, f3 * c4.w);
}

// ---------------- persistent column-partitioned level-loop kernel ----------------
// grid = 8 groups x 18 slots; 512 thr = 4 quads x 4 warps; warp qw owns one 8-col h-block
__global__ void __launch_bounds__(PTHREADS, 1)
persist_kernel(const float* __restrict__ Wh, const float* __restrict__ bh,
               const float* __restrict__ Wp, const float* __restrict__ bp,
               float* __restrict__ out) {
    extern __shared__ uint2 smemB[];
    uint2* B1s = smemB;            // [qw*3+gate][kc][lane]  (12*32*32)
    uint2* B2s = smemB + 12288;    // [qw][kc][lane]         (4*32*32)

    const int t     = threadIdx.x;
    const int warp  = t >> 5;
    const int lane  = t & 31;
    const int gi    = lane >> 2;
    const int tig   = lane & 3;
    const int quad  = warp >> 2;
    const int qw    = warp & 3;
    const int group = blockIdx.x & (NGROUP - 1);
    const int slot  = blockIdx.x >> 3;
    const int qw3   = qw * 3;
    const int c0    = (group << 5) + (qw << 3) + (tig << 1);   // h-col pair this lane owns

    // one-time B slice load into smem
    for (int i = t; i < 16384; i += PTHREADS) {
        uint2 v;
        if (i < 12288) {
            int ln = i & 31, kc = (i >> 5) & 31, r = i >> 10;   // r = qw*3+gate
            int cb = (r % 3) * 32 + group * 4 + (r / 3);
            v = g_Wp1[(kc * 96 + cb) * 32 + ln];
        } else {
            int j = i - 12288;
            int ln = j & 31, kc = (j >> 5) & 31, qq = j >> 10;
            v = g_Wp2[(kc * 32 + group * 4 + qq) * 32 + ln];
        }
        smemB[i] = v;
    }
    __syncthreads();

    const int maxlev = g_maxlev;

    for (int lev = maxlev; lev >= 0; lev--) {
        const int cntI = g_lvlcnt_int[lev];
        if (cntI == 0) continue;
        const int base = g_lvloff[lev];
        const int T = (cntI + 15) >> 4;

        // ===== phase A: GEMM1 (this group's 3x8 gate cols) + cell update =====
        for (int tile = slot * 4 + quad; tile < T; tile += NSLOT * 4) {
            int rA = tile * 16 + gi, rB = rA + 8;
            bool vA = rA < cntI, vB = rB < cntI;
            int gA = vA ? g_order[base + rA] : 0;
            int gB = vB ? g_order[base + rB] : 0;
            const float* pA = vA ? g_hsum + (size_t)gA * MDIM : g_zero;
            const float* pB = vB ? g_hsum + (size_t)gB * MDIM : g_zero;

            float4 accI = make_float4(0.f, 0.f, 0.f, 0.f);
            float4 accO = make_float4(0.f, 0.f, 0.f, 0.f);
            float4 accU = make_float4(0.f, 0.f, 0.f, 0.f);
            #pragma unroll 4
            for (int kc = 0; kc < 32; kc++) {
                int k0 = kc * 8;
                unsigned a0 = tf32u(pA[k0 + tig]);
                unsigned a1 = tf32u(pB[k0 + tig]);
                unsigned a2 = tf32u(pA[k0 + tig + 4]);
                unsigned a3 = tf32u(pB[k0 + tig + 4]);
                uint2 bI = B1s[((qw3 + 0) * 32 + kc) * 32 + lane];
                uint2 bO = B1s[((qw3 + 1) * 32 + kc) * 32 + lane];
                uint2 bU = B1s[((qw3 + 2) * 32 + kc) * 32 + lane];
                mma8(accI, a0, a1, a2, a3, bI.x, bI.y);
                mma8(accO, a0, a1, a2, a3, bO.x, bO.y);
                mma8(accU, a0, a1, a2, a3, bU.x, bU.y);
            }
            if (vA) {
                int tok = g_tok[gA];
                const float* ea = g_EA + (size_t)tok * TM3 + c0;
                float2 eI = *(const float2*)ea;
                float2 eO = *(const float2*)(ea + 256);
                float2 eU = *(const float2*)(ea + 512);
                float2 fc = *(const float2*)(g_fcsum + (size_t)gA * MDIM + c0);
                float cc0 = sigm(accI.x + eI.x) * tanhf(accU.x + eU.x) + fc.x;
                float cc1 = sigm(accI.y + eI.y) * tanhf(accU.y + eU.y) + fc.y;
                float hh0 = sigm(accO.x + eO.x) * tanhf(cc0);
                float hh1 = sigm(accO.y + eO.y) * tanhf(cc1);
                *(float2*)(g_h + (size_t)gA * MDIM + c0) = make_float2(hh0, hh1);
                *(float2*)(g_c + (size_t)gA * MDIM + c0) = make_float2(cc0, cc1);
                if (gA == 0)            *(float2*)(g_rootc + c0)        = make_float2(cc0, cc1);
                else if (gA == N_NODES) *(float2*)(g_rootc + MDIM + c0) = make_float2(cc0, cc1);
            }
            if (vB) {
                int tok = g_tok[gB];
                const float* ea = g_EA + (size_t)tok * TM3 + c0;
                float2 eI = *(const float2*)ea;
                float2 eO = *(const float2*)(ea + 256);
                float2 eU = *(const float2*)(ea + 512);
                float2 fc = *(const float2*)(g_fcsum + (size_t)gB * MDIM + c0);
                float cc0 = sigm(accI.z + eI.x) * tanhf(accU.z + eU.x) + fc.x;
                float cc1 = sigm(accI.w + eI.y) * tanhf(accU.w + eU.y) + fc.y;
                float hh0 = sigm(accO.z + eO.x) * tanhf(cc0);
                float hh1 = sigm(accO.w + eO.y) * tanhf(cc1);
                *(float2*)(g_h + (size_t)gB * MDIM + c0) = make_float2(hh0, hh1);
                *(float2*)(g_c + (size_t)gB * MDIM + c0) = make_float2(cc0, cc1);
                if (gB == 0)            *(float2*)(g_rootc + c0)        = make_float2(cc0, cc1);
                else if (gB == N_NODES) *(float2*)(g_rootc + MDIM + c0) = make_float2(cc0, cc1);
            }
        }
        gsync();   // all groups' h columns visible

        // ===== phase B: GEMM2 (this group's 8 f cols, k over all 256 h cols) + scatter =====
        if (lev > 0) {
            for (int tile = slot * 4 + quad; tile < T; tile += NSLOT * 4) {
                int rA = tile * 16 + gi, rB = rA + 8;
                bool vA = rA < cntI, vB = rB < cntI;
                int gA = vA ? g_order[base + rA] : 0;
                int gB = vB ? g_order[base + rB] : 0;
                const float* pA = vA ? g_h + (size_t)gA * MDIM : g_zero;
                const float* pB = vB ? g_h + (size_t)gB * MDIM : g_zero;

                float4 acc = make_float4(0.f, 0.f, 0.f, 0.f);
                #pragma unroll 4
                for (int kc = 0; kc < 32; kc++) {
                    int k0 = kc * 8;
                    unsigned a0 = tf32u(pA[k0 + tig]);
                    unsigned a1 = tf32u(pB[k0 + tig]);
                    unsigned a2 = tf32u(pA[k0 + tig + 4]);
                    unsigned a3 = tf32u(pB[k0 + tig + 4]);
                    uint2 bb = B2s[(qw * 32 + kc) * 32 + lane];
                    mma8(acc, a0, a1, a2, a3, bb.x, bb.y);
                }
                if (vA && gA != 0 && gA != N_NODES) {
                    int p = g_parent[gA];
                    int ptok = g_tok[p];
                    float2 eb = *(const float2*)(g_EB + (size_t)ptok * MDIM + c0);
                    float f0 = sigm(acc.x + eb.x);
                    float f1 = sigm(acc.y + eb.y);
                    float2 h2 = *(const float2*)(g_h + (size_t)gA * MDIM + c0);
                    float2 c2 = *(const float2*)(g_c + (size_t)gA * MDIM + c0);
                    red2(g_hsum + (size_t)p * MDIM + c0, h2.x, h2.y);
                    red2(g_fcsum + (size_t)p * MDIM + c0, f0 * c2.x, f1 * c2.y);
                }
                if (vB && gB != 0 && gB != N_NODES) {
                    int p = g_parent[gB];
                    int ptok = g_tok[p];
                    float2 eb = *(const float2*)(g_EB + (size_t)ptok * MDIM + c0);
                    float f0 = sigm(acc.z + eb.x);
                    float f1 = sigm(acc.w + eb.y);
                    float2 h2 = *(const float2*)(g_h + (size_t)gB * MDIM + c0);
                    float2 c2 = *(const float2*)(g_c + (size_t)gB * MDIM + c0);
                    red2(g_hsum + (size_t)p * MDIM + c0, h2.x, h2.y);
                    red2(g_fcsum + (size_t)p * MDIM + c0, f0 * c2.x, f1 * c2.y);
                }
            }
            gsync();
        }
    }

    // ===== similarity head (block 0; all 512 threads hit the barriers) =====
    if (blockIdx.x == 0) {
        float* vec = (float*)smemB;        // 512
        float* hid = vec + 512;            // 256
        float* red = hid + 256;            // 16
        if (t < 256) {
            float cl = g_rootc[t], crt = g_rootc[256 + t];
            vec[t] = cl * crt;
            vec[256 + t] = fabsf(cl - crt);
        }
        __syncthreads();
        if (t < 256) {
            float acc = bh[t];
            #pragma unroll 8
            for (int k = 0; k < 512; k++) acc += vec[k] * Wh[(size_t)k * 256 + t];
            hid[t] = 1.f / (1.f + expf(-acc));
        }
        __syncthreads();
        if (t < 256) {
            float p0 = hid[t] * Wp[t * 2 + 0];
            float p1 = hid[t] * Wp[t * 2 + 1];
            #pragma unroll
            for (int o = 16; o > 0; o >>= 1) {
                p0 += __shfl_down_sync(0xffffffffu, p0, o);
                p1 += __shfl_down_sync(0xffffffffu, p1, o);
            }
            if ((t & 31) == 0) { red[t >> 5] = p0; red[8 + (t >> 5)] = p1; }
        }
        __syncthreads();
        if (t == 0) {
            float l0 = bp[0], l1 = bp[1];
            #pragma unroll
            for (int q = 0; q < 8; q++) { l0 += red[q]; l1 += red[8 + q]; }
            float m = fmaxf(l0, l1);
            float e0 = expf(l0 - m), e1 = expf(l1 - m);
            float inv = 1.f / (e0 + e1);
            out[0] = e0 * inv;
            out[1] = e1 * inv;
        }
    }
}

// ---------------- host launch ----------------
extern "C" void kernel_launch(void* const* d_in, const int* in_sizes, int n_in,
                              void* d_out, int out_size) {
    const int*   l_tokens = (const int*)  d_in[0];
    const int*   l_parent = (const int*)  d_in[1];
    const int*   r_tokens = (const int*)  d_in[2];
    const int*   r_parent = (const int*)  d_in[3];
    const float* emb_W    = (const float*)d_in[4];
    const float* Wioux    = (const float*)d_in[5];
    const float* bioux    = (const float*)d_in[6];
    const float* Wiouh    = (const float*)d_in[7];
    const float* biouh    = (const float*)d_in[8];
    const float* Wfx      = (const float*)d_in[9];
    const float* bfx      = (const float*)d_in[10];
    const float* Wfh      = (const float*)d_in[11];
    const float* bfh      = (const float*)d_in[12];
    const float* Wh       = (const float*)d_in[13];
    const float* bh       = (const float*)d_in[14];
    const float* Wp       = (const float*)d_in[15];
    const float* bp       = (const float*)d_in[16];
    float* out = (float*)d_out;

    cudaFuncSetAttribute(persist_kernel,
                         cudaFuncAttributeMaxDynamicSharedMemorySize, SMEM_DYN);

    clear_kernel<<<32768, 256>>>();
    setup_kernel<<<NN / 256, 256>>>(l_tokens, l_parent, r_tokens, r_parent);
    for (int it = 0; it < 6; it++)
        doubling_kernel<<<NN / 256, 256>>>(it & 1);
    hist_kernel<<<NN / 256, 256>>>();
    scan_kernel<<<1, 32>>>();
    scatter_kernel<<<NN / 256, 256>>>();
    pack1_kernel<<<(32 * 96 * 32 + 255) / 256, 256>>>(Wiouh);
    pack2_kernel<<<(32 * 32 * 32 + 255) / 256, 256>>>(Wfh);
    eaeb_kernel<<<dim3(VOCABSZ / 8, 4), 256>>>(emb_W, Wioux, bioux, biouh, Wfx, bfx, bfh);
    leafhc_kernel<<<VOCABSZ, 256>>>();
    leaffh_kernel<<<VOCABSZ / 8, 256>>>(Wfh);
    leafscatter_kernel<<<NN * 64 / 256, 256>>>();

    persist_kernel<<<NBP, PTHREADS, SMEM_DYN>>>(Wh, bh, Wp, bp, out);
}

// round 9
// speedup vs baseline: 2.1694x; 2.1694x over previous
#include <cuda_runtime.h>
#include <cuda_bf16.h>
#include <math.h>

#define N_NODES 65536
#define NN      131072          // both trees
#define MDIM    256
#define TM3     768
#define VOCABSZ 1000
#define MAXLEV  64
#define NB      296             // persistent grid: 2 CTAs/SM on 148 SMs

#define AS_STRIDE 132           // uints (bf16x2 pairs); 132%32=4 -> conflict-free frags

// ---------------- device scratch (static, allowed) ----------------
__device__ float g_hsum[(size_t)NN * MDIM];
__device__ float g_fcsum[(size_t)NN * MDIM];
__device__ float g_EA[(size_t)VOCABSZ * TM3];
__device__ float g_EB[(size_t)VOCABSZ * MDIM];
__device__ float g_HL[(size_t)VOCABSZ * MDIM];
__device__ float g_CL[(size_t)VOCABSZ * MDIM];
__device__ float g_FH[(size_t)VOCABSZ * MDIM];
__device__ float g_rootc[2 * MDIM];

// fragment-packed bf16 weights: [kc16][colblock][lane] -> (b0,b1) each = 2 bf16
__device__ uint2 g_Wp1[16 * 96 * 32];   // Wiouh, 768 cols = 96 colblocks
__device__ uint2 g_Wp2[16 * 32 * 32];   // Wfh,   256 cols = 32 colblocks

__device__ int g_parent[NN];
__device__ int g_tok[NN];
__device__ int g_anc[2][NN];
__device__ int g_dist[2][NN];
__device__ int g_childcnt[NN];
__device__ int g_lvlcnt_int[MAXLEV];
__device__ int g_lvlcnt_leaf[MAXLEV];
__device__ int g_lvloff[MAXLEV];
__device__ int g_curs_int[MAXLEV];
__device__ int g_curs_leaf[MAXLEV];
__device__ int g_order[NN];
__device__ int g_maxlev;

__device__ unsigned g_bcount = 0;
__device__ volatile unsigned g_bgen = 0;

__device__ __forceinline__ float sigm(float x) { return 1.f / (1.f + __expf(-x)); }

__device__ __forceinline__ unsigned bfpack(float lo, float hi) {
    __nv_bfloat162 v = __floats2bfloat162_rn(lo, hi);
    return *(unsigned*)&v;
}
__device__ __forceinline__ float2 bfunpack(unsigned u) {
    __nv_bfloat162 v = *(__nv_bfloat162*)&u;
    return __bfloat1622float2(v);
}

__device__ __forceinline__ void mma16(float4& d, unsigned a0, unsigned a1, unsigned a2, unsigned a3,
                                      unsigned b0, unsigned b1) {
    asm volatile("mma.sync.aligned.m16n8k16.row.col.f32.bf16.bf16.f32 "
        "{%0,%1,%2,%3},{%4,%5,%6,%7},{%8,%9},{%0,%1,%2,%3};"
        : "+f"(d.x), "+f"(d.y), "+f"(d.z), "+f"(d.w)
        : "r"(a0), "r"(a1), "r"(a2), "r"(a3), "r"(b0), "r"(b1));
}

__device__ __forceinline__ void red2(float* p, float a, float b) {
    asm volatile("red.global.add.v2.f32 [%0], {%1, %2};"
                 :: "l"(p), "f"(a), "f"(b) : "memory");
}
__device__ __forceinline__ void red4(float* p, float a, float b, float c, float d) {
    asm volatile("red.global.add.v4.f32 [%0], {%1, %2, %3, %4};"
                 :: "l"(p), "f"(a), "f"(b), "f"(c), "f"(d) : "memory");
}

__device__ __forceinline__ void gsync() {
    __syncthreads();
    if (threadIdx.x == 0) {
        __threadfence();
        unsigned my = g_bgen;
        if (atomicInc(&g_bcount, gridDim.x - 1) == gridDim.x - 1) {
            g_bgen = my + 1;
        } else {
            while (g_bgen == my) { }
        }
        __threadfence();
    }
    __syncthreads();
}

// ---------------- setup ----------------
__global__ void clear_kernel() {
    size_t i = (size_t)blockIdx.x * blockDim.x + threadIdx.x;
    size_t tot4 = (size_t)NN * MDIM / 4;
    if (i < tot4) {
        float4 z = make_float4(0.f, 0.f, 0.f, 0.f);
        reinterpret_cast<float4*>(g_hsum)[i] = z;
        reinterpret_cast<float4*>(g_fcsum)[i] = z;
    }
    if (i < NN) g_childcnt[i] = 0;
    if (i < MAXLEV) {
        g_lvlcnt_int[i] = 0; g_lvlcnt_leaf[i] = 0;
        g_curs_int[i] = 0;   g_curs_leaf[i] = 0;
    }
}

__global__ void setup_kernel(const int* __restrict__ lt, const int* __restrict__ lp,
                             const int* __restrict__ rt, const int* __restrict__ rp) {
    int g = blockIdx.x * blockDim.x + threadIdx.x;
    if (g >= NN) return;
    int tok, par; bool root;
    if (g < N_NODES) {
        tok = lt[g]; root = (g == 0);
        par = root ? g : lp[g];
    } else {
        int i = g - N_NODES;
        tok = rt[i]; root = (i == 0);
        par = root ? g : (N_NODES + rp[i]);
    }
    g_tok[g] = tok; g_parent[g] = par;
    g_anc[0][g] = par;
    g_dist[0][g] = root ? 0 : 1;
    if (!root) atomicAdd(&g_childcnt[par], 1);
}

__global__ void doubling_kernel(int src) {
    int g = blockIdx.x * blockDim.x + threadIdx.x;
    if (g >= NN) return;
    int a = g_anc[src][g];
    g_dist[1 - src][g] = g_dist[src][g] + g_dist[src][a];
    g_anc[1 - src][g]  = g_anc[src][a];
}

__global__ void hist_kernel() {
    int g = blockIdx.x * blockDim.x + threadIdx.x;
    if (g >= NN) return;
    int d = g_dist[0][g]; if (d > MAXLEV - 1) d = MAXLEV - 1;
    if (g_childcnt[g] > 0) atomicAdd(&g_lvlcnt_int[d], 1);
    else                   atomicAdd(&g_lvlcnt_leaf[d], 1);
}

__global__ void scan_kernel() {
    if (threadIdx.x == 0) {
        int off = 0, maxl = 0;
        for (int l = 0; l < MAXLEV; l++) {
            g_lvloff[l] = off;
            int c = g_lvlcnt_int[l] + g_lvlcnt_leaf[l];
            if (c > 0) maxl = l;
            off += c;
        }
        g_maxlev = maxl;
    }
}

__global__ void scatter_kernel() {
    int g = blockIdx.x * blockDim.x + threadIdx.x;
    if (g >= NN) return;
    int d = g_dist[0][g]; if (d > MAXLEV - 1) d = MAXLEV - 1;
    int base = g_lvloff[d];
    if (g_childcnt[g] > 0) {
        int p = atomicAdd(&g_curs_int[d], 1);
        g_order[base + p] = g;
    } else {
        int p = atomicAdd(&g_curs_leaf[d], 1);
        g_order[base + g_lvlcnt_int[d] + p] = g;
    }
}

// weight pack: lane holds b0 = (W[k0+2tig][col], W[k0+2tig+1][col]); b1 rows +8
__global__ void pack1_kernel(const float* __restrict__ W) {   // Wiouh 256x768
    int idx = blockIdx.x * blockDim.x + threadIdx.x;
    if (idx >= 16 * 96 * 32) return;
    int lane = idx & 31;
    int cbi = (idx >> 5) % 96;
    int kc = idx / (96 * 32);
    int tig = lane & 3, gi = lane >> 2;
    int col = cbi * 8 + gi;
    int k0 = kc * 16 + 2 * tig;
    unsigned b0 = bfpack(W[(size_t)k0 * TM3 + col],       W[(size_t)(k0 + 1) * TM3 + col]);
    unsigned b1 = bfpack(W[(size_t)(k0 + 8) * TM3 + col], W[(size_t)(k0 + 9) * TM3 + col]);
    g_Wp1[idx] = make_uint2(b0, b1);
}
__global__ void pack2_kernel(const float* __restrict__ W) {   // Wfh 256x256
    int idx = blockIdx.x * blockDim.x + threadIdx.x;
    if (idx >= 16 * 32 * 32) return;
    int lane = idx & 31;
    int cbi = (idx >> 5) % 32;
    int kc = idx / (32 * 32);
    int tig = lane & 3, gi = lane >> 2;
    int col = cbi * 8 + gi;
    int k0 = kc * 16 + 2 * tig;
    unsigned b0 = bfpack(W[(size_t)k0 * MDIM + col],       W[(size_t)(k0 + 1) * MDIM + col]);
    unsigned b1 = bfpack(W[(size_t)(k0 + 8) * MDIM + col], W[(size_t)(k0 + 9) * MDIM + col]);
    g_Wp2[idx] = make_uint2(b0, b1);
}

// EA/EB: tiled over 8 vocab rows per block (weight reuse x8)
__global__ void eaeb_kernel(const float* __restrict__ emb,
                            const float* __restrict__ Wioux, const float* __restrict__ bioux,
                            const float* __restrict__ biouh,
                            const float* __restrict__ Wfx, const float* __restrict__ bfx,
                            const float* __restrict__ bfh) {
    int v0 = blockIdx.x * 8;
    int chunk = blockIdx.y;
    __shared__ float xs[8][MDIM];
    int t = threadIdx.x;
    #pragma unroll
    for (int i = 0; i < 8; i++) {
        int idx = t + i * 256;
        xs[idx >> 8][idx & 255] = emb[(size_t)v0 * MDIM + idx];
    }
    __syncthreads();
    float acc[8];
    #pragma unroll
    for (int r = 0; r < 8; r++) acc[r] = 0.f;
    if (chunk < 3) {
        int j = chunk * 256 + t;
        for (int k = 0; k < MDIM; k++) {
            float w = Wioux[(size_t)k * TM3 + j];
            #pragma unroll
            for (int r = 0; r < 8; r++) acc[r] += xs[r][k] * w;
        }
        float bias = bioux[j] + biouh[j];
        #pragma unroll
        for (int r = 0; r < 8; r++)
            g_EA[(size_t)(v0 + r) * TM3 + j] = acc[r] + bias;
    } else {
        int j = t;
        for (int k = 0; k < MDIM; k++) {
            float w = Wfx[(size_t)k * MDIM + j];
            #pragma unroll
            for (int r = 0; r < 8; r++) acc[r] += xs[r][k] * w;
        }
        float bias = bfx[j] + bfh[j];
        #pragma unroll
        for (int r = 0; r < 8; r++)
            g_EB[(size_t)(v0 + r) * MDIM + j] = acc[r] + bias;
    }
}

__global__ void leafhc_kernel() {
    int v = blockIdx.x, t = threadIdx.x;
    const float* ea = &g_EA[(size_t)v * TM3];
    float cc = sigm(ea[t]) * tanhf(ea[512 + t]);
    float hh = sigm(ea[256 + t]) * tanhf(cc);
    g_CL[(size_t)v * MDIM + t] = cc;
    g_HL[(size_t)v * MDIM + t] = hh;
}

// FH = HL @ Wfh, tiled over 8 vocab rows
__global__ void leaffh_kernel(const float* __restrict__ Wfh) {
    int v0 = blockIdx.x * 8;
    int t = threadIdx.x;
    __shared__ float hs[8][MDIM];
    #pragma unroll
    for (int i = 0; i < 8; i++) {
        int idx = t + i * 256;
        hs[idx >> 8][idx & 255] = g_HL[(size_t)v0 * MDIM + idx];
    }
    __syncthreads();
    float acc[8];
    #pragma unroll
    for (int r = 0; r < 8; r++) acc[r] = 0.f;
    for (int k = 0; k < MDIM; k++) {
        float w = Wfh[(size_t)k * MDIM + t];
        #pragma unroll
        for (int r = 0; r < 8; r++) acc[r] += hs[r][k] * w;
    }
    #pragma unroll
    for (int r = 0; r < 8; r++)
        g_FH[(size_t)(v0 + r) * MDIM + t] = acc[r];
}

__global__ void leafscatter_kernel() {
    int idx = blockIdx.x * blockDim.x + threadIdx.x;
    int g = idx >> 6;
    int c = (idx & 63) * 4;
    if (g >= NN) return;
    if (g_childcnt[g] > 0) return;
    int p = g_parent[g];
    int tok = g_tok[g], ptok = g_tok[p];
    float4 h4 = *(const float4*)&g_HL[(size_t)tok * MDIM + c];
    float4 c4 = *(const float4*)&g_CL[(size_t)tok * MDIM + c];
    float4 fh = *(const float4*)&g_FH[(size_t)tok * MDIM + c];
    float4 eb = *(const float4*)&g_EB[(size_t)ptok * MDIM + c];
    float f0 = sigm(fh.x + eb.x), f1 = sigm(fh.y + eb.y);
    float f2 = sigm(fh.z + eb.z), f3 = sigm(fh.w + eb.w);
    red4(&g_hsum[(size_t)p * MDIM + c], h4.x, h4.y, h4.z, h4.w);
    red4(&g_fcsum[(size_t)p * MDIM + c], f0 * c4.x, f1 * c4.y, f2 * c4.z, f3 * c4.w);
}

// ---------------- persistent bf16 tensor-core level-loop kernel ----------------
__global__ void __launch_bounds__(256, 2)
persist_kernel(const float* __restrict__ Wh, const float* __restrict__ bh,
               const float* __restrict__ Wp, const float* __restrict__ bp,
               float* __restrict__ out) {
    __shared__ unsigned AsU[16 * AS_STRIDE];   // bf16x2 pairs: h_sum, then h
    __shared__ int gidS[16], parS[16], tokS[16], ptokS[16];

    const int t    = threadIdx.x;
    const int w    = t >> 5;
    const int lane = t & 31;
    const int gi   = lane >> 2;
    const int tig  = lane & 3;
    const int maxlev = g_maxlev;

    for (int lev = maxlev; lev >= 0; lev--) {
        const int cntI = g_lvlcnt_int[lev];
        if (cntI == 0) continue;
        const int base = g_lvloff[lev];
        const int tiles = (cntI + 15) >> 4;

        for (int tile = blockIdx.x; tile < tiles; tile += gridDim.x) {
            int r0 = tile * 16;
            int nr = min(16, cntI - r0);
            if (t < 16) {
                int g = (t < nr) ? g_order[base + r0 + t] : 0;
                gidS[t] = g;
                int p = g_parent[g];
                parS[t] = p;
                tokS[t] = g_tok[g];
                ptokS[t] = g_tok[p];
            }
            __syncthreads();
            // stage A = h_sum rows as bf16x2 (16 rows x 128 pairs = 512 uint4)
            #pragma unroll
            for (int i = 0; i < 2; i++) {
                int fi = t + i * 256;            // uint4 index 0..511
                int r = fi >> 5, p4 = fi & 31;   // 32 uint4 per row
                uint4 u;
                if (r < nr) {
                    const float4* src = (const float4*)(g_hsum + (size_t)gidS[r] * MDIM + p4 * 8);
                    float4 v0 = src[0], v1 = src[1];
                    u = make_uint4(bfpack(v0.x, v0.y), bfpack(v0.z, v0.w),
                                   bfpack(v1.x, v1.y), bfpack(v1.z, v1.w));
                } else u = make_uint4(0, 0, 0, 0);
                *(uint4*)&AsU[r * AS_STRIDE + p4 * 4] = u;
            }
            __syncthreads();

            // ===== GEMM1: iou[16x768] = A @ Wiouh (bf16 mma, B from packed L2) =====
            float4 accI[4], accO[4], accU[4];
            #pragma unroll
            for (int b = 0; b < 4; b++) {
                accI[b] = make_float4(0.f, 0.f, 0.f, 0.f);
                accO[b] = make_float4(0.f, 0.f, 0.f, 0.f);
                accU[b] = make_float4(0.f, 0.f, 0.f, 0.f);
            }
            #pragma unroll 2
            for (int kc = 0; kc < 16; kc++) {
                int k8 = kc * 8;                 // pair offset within row
                unsigned a0 = AsU[gi * AS_STRIDE + k8 + tig];
                unsigned a1 = AsU[(gi + 8) * AS_STRIDE + k8 + tig];
                unsigned a2 = AsU[gi * AS_STRIDE + k8 + tig + 4];
                unsigned a3 = AsU[(gi + 8) * AS_STRIDE + k8 + tig + 4];
                const uint2* wp = g_Wp1 + (size_t)kc * 96 * 32 + lane;
                #pragma unroll
                for (int b = 0; b < 4; b++) {
                    int cbi = w + 8 * b;
                    uint2 bI = wp[(size_t)cbi * 32];
                    uint2 bO = wp[(size_t)(cbi + 32) * 32];
                    uint2 bU = wp[(size_t)(cbi + 64) * 32];
                    mma16(accI[b], a0, a1, a2, a3, bI.x, bI.y);
                    mma16(accO[b], a0, a1, a2, a3, bO.x, bO.y);
                    mma16(accU[b], a0, a1, a2, a3, bU.x, bU.y);
                }
            }
            __syncthreads();   // all A reads done before overwriting As with h

            // ===== cell update (h -> As bf16x2, c kept fp32 in regs) =====
            float ccr[16];
            #pragma unroll
            for (int b = 0; b < 4; b++) {
                int c0 = 8 * w + 64 * b + 2 * tig;
                #pragma unroll
                for (int rr = 0; rr < 2; rr++) {
                    int r = gi + rr * 8;
                    int g = gidS[r];
                    int tok = tokS[r];
                    float vI0 = rr ? accI[b].z : accI[b].x;
                    float vI1 = rr ? accI[b].w : accI[b].y;
                    float vO0 = rr ? accO[b].z : accO[b].x;
                    float vO1 = rr ? accO[b].w : accO[b].y;
                    float vU0 = rr ? accU[b].z : accU[b].x;
                    float vU1 = rr ? accU[b].w : accU[b].y;
                    const float* ea = g_EA + (size_t)tok * TM3 + c0;
                    float2 eI = *(const float2*)ea;
                    float2 eO = *(const float2*)(ea + 256);
                    float2 eU = *(const float2*)(ea + 512);
                    float2 fc = *(const float2*)(g_fcsum + (size_t)g * MDIM + c0);
                    float cc0 = sigm(vI0 + eI.x) * tanhf(vU0 + eU.x) + fc.x;
                    float cc1 = sigm(vI1 + eI.y) * tanhf(vU1 + eU.y) + fc.y;
                    float hh0 = sigm(vO0 + eO.x) * tanhf(cc0);
                    float hh1 = sigm(vO1 + eO.y) * tanhf(cc1);
                    AsU[r * AS_STRIDE + (c0 >> 1)] = bfpack(hh0, hh1);
                    int ix = b * 4 + rr * 2;
                    ccr[ix] = cc0; ccr[ix + 1] = cc1;
                    if (r < nr) {
                        if (g == 0) {
                            g_rootc[c0] = cc0; g_rootc[c0 + 1] = cc1;
                        } else if (g == N_NODES) {
                            g_rootc[MDIM + c0] = cc0; g_rootc[MDIM + c0 + 1] = cc1;
                        }
                    }
                }
            }
            __syncthreads();

            // ===== GEMM2: fpre[16x256] = h @ Wfh + parent scatter =====
            if (lev > 0) {
                float4 acc2[4];
                #pragma unroll
                for (int b = 0; b < 4; b++) acc2[b] = make_float4(0.f, 0.f, 0.f, 0.f);
                #pragma unroll 2
                for (int kc = 0; kc < 16; kc++) {
                    int k8 = kc * 8;
                    unsigned a0 = AsU[gi * AS_STRIDE + k8 + tig];
                    unsigned a1 = AsU[(gi + 8) * AS_STRIDE + k8 + tig];
                    unsigned a2 = AsU[gi * AS_STRIDE + k8 + tig + 4];
                    unsigned a3 = AsU[(gi + 8) * AS_STRIDE + k8 + tig + 4];
                    const uint2* wp = g_Wp2 + (size_t)kc * 32 * 32 + lane;
                    #pragma unroll
                    for (int b = 0; b < 4; b++) {
                        uint2 bb = wp[(size_t)(w + 8 * b) * 32];
                        mma16(acc2[b], a0, a1, a2, a3, bb.x, bb.y);
                    }
                }
                #pragma unroll
                for (int b = 0; b < 4; b++) {
                    int c0 = 8 * w + 64 * b + 2 * tig;
                    #pragma unroll
                    for (int rr = 0; rr < 2; rr++) {
                        int r = gi + rr * 8;
                        if (r < nr) {
                            int g = gidS[r];
                            if (g != 0 && g != N_NODES) {
                                int p = parS[r];
                                float2 eb = *(const float2*)(g_EB + (size_t)ptokS[r] * MDIM + c0);
                                float F0 = rr ? acc2[b].z : acc2[b].x;
                                float F1 = rr ? acc2[b].w : acc2[b].y;
                                float f0 = sigm(F0 + eb.x);
                                float f1 = sigm(F1 + eb.y);
                                float2 h2 = bfunpack(AsU[r * AS_STRIDE + (c0 >> 1)]);
                                int ix = b * 4 + rr * 2;
                                red2(g_hsum + (size_t)p * MDIM + c0, h2.x, h2.y);
                                red2(g_fcsum + (size_t)p * MDIM + c0, f0 * ccr[ix], f1 * ccr[ix + 1]);
                            }
                        }
                    }
                }
            }
            __syncthreads();
        }
        gsync();
    }

    // ===== similarity head (block 0) =====
    if (blockIdx.x == 0) {
        float* vec = (float*)AsU;          // 512
        float* hid = vec + 512;            // 256
        float* red = hid + 256;            // 16
        float cl = g_rootc[t], crt = g_rootc[256 + t];
        vec[t] = cl * crt;
        vec[256 + t] = fabsf(cl - crt);
        __syncthreads();
        float acc = bh[t];
        #pragma unroll 8
        for (int k = 0; k < 512; k++) acc += vec[k] * Wh[(size_t)k * 256 + t];
        hid[t] = 1.f / (1.f + expf(-acc));
        __syncthreads();
        float p0 = hid[t] * Wp[t * 2 + 0];
        float p1 = hid[t] * Wp[t * 2 + 1];
        #pragma unroll
        for (int o = 16; o > 0; o >>= 1) {
            p0 += __shfl_down_sync(0xffffffffu, p0, o);
            p1 += __shfl_down_sync(0xffffffffu, p1, o);
        }
        if ((t & 31) == 0) { red[t >> 5] = p0; red[8 + (t >> 5)] = p1; }
        __syncthreads();
        if (t == 0) {
            float l0 = bp[0], l1 = bp[1];
            #pragma unroll
            for (int q = 0; q < 8; q++) { l0 += red[q]; l1 += red[8 + q]; }
            float m = fmaxf(l0, l1);
            float e0 = expf(l0 - m), e1 = expf(l1 - m);
            float inv = 1.f / (e0 + e1);
            out[0] = e0 * inv;
            out[1] = e1 * inv;
        }
    }
}

// ---------------- host launch ----------------
extern "C" void kernel_launch(void* const* d_in, const int* in_sizes, int n_in,
                              void* d_out, int out_size) {
    const int*   l_tokens = (const int*)  d_in[0];
    const int*   l_parent = (const int*)  d_in[1];
    const int*   r_tokens = (const int*)  d_in[2];
    const int*   r_parent = (const int*)  d_in[3];
    const float* emb_W    = (const float*)d_in[4];
    const float* Wioux    = (const float*)d_in[5];
    const float* bioux    = (const float*)d_in[6];
    const float* Wiouh    = (const float*)d_in[7];
    const float* biouh    = (const float*)d_in[8];
    const float* Wfx      = (const float*)d_in[9];
    const float* bfx      = (const float*)d_in[10];
    const float* Wfh      = (const float*)d_in[11];
    const float* bfh      = (const float*)d_in[12];
    const float* Wh       = (const float*)d_in[13];
    const float* bh       = (const float*)d_in[14];
    const float* Wp       = (const float*)d_in[15];
    const float* bp       = (const float*)d_in[16];
    float* out = (float*)d_out;

    clear_kernel<<<32768, 256>>>();
    setup_kernel<<<NN / 256, 256>>>(l_tokens, l_parent, r_tokens, r_parent);
    for (int it = 0; it < 6; it++)
        doubling_kernel<<<NN / 256, 256>>>(it & 1);
    hist_kernel<<<NN / 256, 256>>>();
    scan_kernel<<<1, 32>>>();
    scatter_kernel<<<NN / 256, 256>>>();
    pack1_kernel<<<(16 * 96 * 32 + 255) / 256, 256>>>(Wiouh);
    pack2_kernel<<<(16 * 32 * 32 + 255) / 256, 256>>>(Wfh);
    eaeb_kernel<<<dim3(VOCABSZ / 8, 4), 256>>>(emb_W, Wioux, bioux, biouh, Wfx, bfx, bfh);
    leafhc_kernel<<<VOCABSZ, 256>>>();
    leaffh_kernel<<<VOCABSZ / 8, 256>>>(Wfh);
    leafscatter_kernel<<<NN * 64 / 256, 256>>>();

    persist_kernel<<<NB, 256>>>(Wh, bh, Wp, bp, out);
}